// round 3
// baseline (speedup 1.0000x reference)
#include <cuda_runtime.h>
#include <cuda_bf16.h>

// ---------------- problem constants ----------------
#define BATCH  256
#define NPIX   49152
#define NRET   3072
#define NLGN   3072
#define NV1    6144
#define NIT    3072
#define NCLS   1000
#define NK     NIT          // classifier K = 3072

#define MAX1   128          // max nnz per V1 row (lambda ~31)
#define MAX2   256          // max nnz per IT row (lambda ~62)
#define KSPLIT 8

// ---------------- device scratch (no runtime allocation allowed) ----------------
__device__ float g_r2t[NRET * BATCH];     // LGN output, [n, b]
__device__ float g_r3t[NV1 * BATCH];      // V1 output,  [n, b]
__device__ float g_r4t[NIT * BATCH];      // IT output,  [n, b]
__device__ float g_sums[NRET + NV1 + NIT];// s_lgn | s_v1 | s_it
__device__ int   g_idx1[NV1 * MAX1];
__device__ int   g_cnt1[NV1];
__device__ int   g_idx2[NIT * MAX2];
__device__ int   g_cnt2[NIT];
__device__ float g_part[KSPLIT * BATCH * NCLS]; // split-K partials

__device__ __forceinline__ float sigmoidf_(float z) {
    return 1.0f / (1.0f + __expf(-z));
}

// ---------------- kernel A: per-neuron weight sums ----------------
__global__ void sums_kernel(const float* __restrict__ w_lgn,
                            const float* __restrict__ w_v1,
                            const float* __restrict__ w_it,
                            float* __restrict__ sums) {
    int i = blockIdx.x * blockDim.x + threadIdx.x;
    if (i < NRET) {
        float s = 0.f;
        #pragma unroll
        for (int k = 0; k < 16; k++) s += w_lgn[i * 16 + k];
        sums[i] = s;
    } else if (i < NRET + NV1) {
        int j = i - NRET;
        float s = 0.f;
        #pragma unroll
        for (int k = 0; k < 32; k++) s += w_v1[j * 32 + k];
        sums[NRET + j] = s;
    } else if (i < NRET + NV1 + NIT) {
        int j = i - NRET - NV1;
        float s = 0.f;
        #pragma unroll
        for (int k = 0; k < 32; k++) s += w_it[j * 32 + k];
        sums[NRET + NV1 + j] = s;
    }
}

// ---------------- kernel B: retina + LGN fused ----------------
// grid (NRET/256, BATCH), block 256. Output transposed [n, b].
__global__ void retina_lgn_kernel(const float* __restrict__ x,
                                  const int* __restrict__ pm,
                                  const float* __restrict__ w_ret,
                                  const float* __restrict__ b_ret,
                                  const float* __restrict__ s_lgn,
                                  const float* __restrict__ b_lgn,
                                  float* __restrict__ r2t) {
    int n = blockIdx.x * blockDim.x + threadIdx.x;
    int b = blockIdx.y;
    if (n >= NRET) return;
    const float* xb = x + (long long)b * NPIX;
    const int4*  pm4 = (const int4*)(pm + n * 16);
    const float4* w4 = (const float4*)(w_ret + n * 16);
    float acc = 0.f;
    #pragma unroll
    for (int q = 0; q < 4; q++) {
        int4   p = pm4[q];
        float4 w = w4[q];
        acc += xb[p.x] * w.x + xb[p.y] * w.y + xb[p.z] * w.z + xb[p.w] * w.w;
    }
    float r1 = sigmoidf_(acc - b_ret[n]);
    float r2 = sigmoidf_(r1 * s_lgn[n] - b_lgn[n]);
    r2t[n * BATCH + b] = r2;
}

// ---------------- kernel C: deterministic CSR build (warp per row, ballot compaction) ----------------
__global__ void build_csr_kernel(const int* __restrict__ m, int rows, int cols,
                                 int maxnnz, int* __restrict__ idx,
                                 int* __restrict__ cnt) {
    int warp = (blockIdx.x * blockDim.x + threadIdx.x) >> 5;
    int lane = threadIdx.x & 31;
    if (warp >= rows) return;
    const int* row = m + (long long)warp * cols;
    int* out = idx + (long long)warp * maxnnz;
    int c = 0;
    for (int c0 = 0; c0 < cols; c0 += 32) {
        int v = row[c0 + lane];
        unsigned msk = __ballot_sync(0xffffffffu, v != 0);
        if (v) {
            int pos = c + __popc(msk & ((1u << lane) - 1));
            if (pos < maxnnz) out[pos] = c0 + lane;
        }
        c += __popc(msk);
    }
    if (lane == 0) cnt[warp] = (c < maxnnz) ? c : maxnnz;
}

// ---------------- kernel D: sparse mean + sigmoid (block per output row, thread per batch) ----------------
__global__ void spmm_act_kernel(const int* __restrict__ idx,
                                const int* __restrict__ cnt,
                                int maxnnz,
                                const float* __restrict__ src,  // [nin, BATCH]
                                const float* __restrict__ s,    // per-row weight sum
                                const float* __restrict__ bias,
                                float* __restrict__ dst) {      // [rows, BATCH]
    int j = blockIdx.x;
    int b = threadIdx.x;
    int n = cnt[j];
    const int* ji = idx + (long long)j * maxnnz;
    float acc = 0.f;
    int k = 0;
    for (; k + 4 <= n; k += 4) {
        int i0 = ji[k], i1 = ji[k + 1], i2 = ji[k + 2], i3 = ji[k + 3];
        acc += src[i0 * BATCH + b] + src[i1 * BATCH + b]
             + src[i2 * BATCH + b] + src[i3 * BATCH + b];
    }
    for (; k < n; k++) acc += src[ji[k] * BATCH + b];
    float v = acc / (float)n;
    float z = v * s[j] - bias[j];
    dst[j * BATCH + b] = sigmoidf_(z);
}

// ---------------- kernel E: classifier GEMM, split-K, tiled fp32 ----------------
// out[c, b] partials; A = r4t [NK, BATCH], W = W_cls [NCLS, NK]
#define TC 64
#define TB 64
#define TKK 32
__global__ void cls_gemm_kernel(const float* __restrict__ A,
                                const float* __restrict__ W,
                                float* __restrict__ part) {
    __shared__ float As[TKK][TB];      // [k][b]
    __shared__ float Ws[TKK][TC + 4];  // [k][c], padded
    int tid = threadIdx.x;
    int c0 = blockIdx.x * TC;
    int b0 = blockIdx.y * TB;
    int ks = blockIdx.z;
    int kbase = ks * (NK / KSPLIT);
    int tx = tid & 15;   // b micro group
    int ty = tid >> 4;   // c micro group
    float acc[4][4] = {};
    for (int kt = 0; kt < (NK / KSPLIT); kt += TKK) {
        int k0 = kbase + kt;
        // load A tile 32x64 (coalesced)
        #pragma unroll
        for (int i = 0; i < (TKK * TB) / 256; i++) {
            int id = tid + i * 256;
            int r = id >> 6, col = id & 63;
            As[r][col] = A[(k0 + r) * BATCH + b0 + col];
        }
        // load W tile 64(c) x 32(k), stored transposed as Ws[k][c]
        #pragma unroll
        for (int i = 0; i < (TKK * TC) / 256; i++) {
            int id = tid + i * 256;
            int r = id >> 5, col = id & 31;   // r = c offset, col = k offset
            int c = c0 + r;
            Ws[col][r] = (c < NCLS) ? W[(long long)c * NK + k0 + col] : 0.f;
        }
        __syncthreads();
        #pragma unroll
        for (int kk = 0; kk < TKK; kk++) {
            float4 av = *(const float4*)&As[kk][tx * 4];
            float4 wv = *(const float4*)&Ws[kk][ty * 4];
            float a[4] = {av.x, av.y, av.z, av.w};
            float w[4] = {wv.x, wv.y, wv.z, wv.w};
            #pragma unroll
            for (int i = 0; i < 4; i++)
                #pragma unroll
                for (int j = 0; j < 4; j++)
                    acc[i][j] += w[i] * a[j];
        }
        __syncthreads();
    }
    #pragma unroll
    for (int i = 0; i < 4; i++) {
        int c = c0 + ty * 4 + i;
        if (c < NCLS) {
            #pragma unroll
            for (int j = 0; j < 4; j++) {
                int b = b0 + tx * 4 + j;
                part[((long long)ks * BATCH + b) * NCLS + c] = acc[i][j];
            }
        }
    }
}

// ---------------- kernel F: split-K reduce + bias ----------------
__global__ void reduce_kernel(const float* __restrict__ part,
                              const float* __restrict__ b_cls,
                              float* __restrict__ out) {
    int id = blockIdx.x * blockDim.x + threadIdx.x;
    if (id >= BATCH * NCLS) return;
    int c = id % NCLS;
    float acc = b_cls[c];
    #pragma unroll
    for (int ks = 0; ks < KSPLIT; ks++)
        acc += part[(long long)ks * BATCH * NCLS + id];
    out[id] = acc;
}

// ---------------- launch ----------------
extern "C" void kernel_launch(void* const* d_in, const int* in_sizes, int n_in,
                              void* d_out, int out_size) {
    const float* x        = (const float*)d_in[0];
    const float* w_ret    = (const float*)d_in[1];
    const float* b_ret    = (const float*)d_in[2];
    const float* w_lgn    = (const float*)d_in[3];
    const float* b_lgn    = (const float*)d_in[4];
    const float* w_v1     = (const float*)d_in[5];
    const float* b_v1     = (const float*)d_in[6];
    const float* w_it     = (const float*)d_in[7];
    const float* b_it     = (const float*)d_in[8];
    const float* W_cls    = (const float*)d_in[9];
    const float* b_cls    = (const float*)d_in[10];
    const int*   pixel_map= (const int*)d_in[11];
    const int*   m1       = (const int*)d_in[12];
    const int*   m2       = (const int*)d_in[13];
    float* out = (float*)d_out;

    float* r2t = nullptr; float* r3t = nullptr; float* r4t = nullptr;
    float* sums = nullptr; float* partp = nullptr;
    int *idx1 = nullptr, *cnt1 = nullptr, *idx2 = nullptr, *cnt2 = nullptr;
    cudaGetSymbolAddress((void**)&r2t,  g_r2t);
    cudaGetSymbolAddress((void**)&r3t,  g_r3t);
    cudaGetSymbolAddress((void**)&r4t,  g_r4t);
    cudaGetSymbolAddress((void**)&sums, g_sums);
    cudaGetSymbolAddress((void**)&partp,g_part);
    cudaGetSymbolAddress((void**)&idx1, g_idx1);
    cudaGetSymbolAddress((void**)&cnt1, g_cnt1);
    cudaGetSymbolAddress((void**)&idx2, g_idx2);
    cudaGetSymbolAddress((void**)&cnt2, g_cnt2);

    // A: weight sums
    sums_kernel<<<(NRET + NV1 + NIT + 255) / 256, 256>>>(w_lgn, w_v1, w_it, sums);
    // C: CSR builds (independent of A/B)
    build_csr_kernel<<<(NV1 * 32 + 255) / 256, 256>>>(m1, NV1, NLGN, MAX1, idx1, cnt1);
    build_csr_kernel<<<(NIT * 32 + 255) / 256, 256>>>(m2, NIT, NV1, MAX2, idx2, cnt2);
    // B: retina + LGN
    {
        dim3 grid(NRET / 256, BATCH);
        retina_lgn_kernel<<<grid, 256>>>(x, pixel_map, w_ret, b_ret,
                                         sums /*s_lgn*/, b_lgn, r2t);
    }
    // D1: V1
    spmm_act_kernel<<<NV1, BATCH>>>(idx1, cnt1, MAX1, r2t,
                                    sums + NRET, b_v1, r3t);
    // D2: IT
    spmm_act_kernel<<<NIT, BATCH>>>(idx2, cnt2, MAX2, r3t,
                                    sums + NRET + NV1, b_it, r4t);
    // E: classifier split-K GEMM
    {
        dim3 grid((NCLS + TC - 1) / TC, BATCH / TB, KSPLIT);
        cls_gemm_kernel<<<grid, 256>>>(r4t, W_cls, partp);
    }
    // F: reduce + bias
    reduce_kernel<<<(BATCH * NCLS + 255) / 256, 256>>>(partp, b_cls, out);
    (void)in_sizes; (void)n_in; (void)out_size;
}

// round 6
// speedup vs baseline: 1.1549x; 1.1549x over previous
#include <cuda_runtime.h>
#include <cuda_fp16.h>
#include <cuda_bf16.h>

// ---------------- problem constants ----------------
#define BATCH  256
#define NPIX   49152
#define NRET   3072
#define NLGN   3072
#define NV1    6144
#define NIT    3072
#define NCLS   1000
#define NCLSP  1024         // padded classes
#define NK     NIT          // classifier K = 3072

#define MAX1   128
#define MAX2   256
#define KSPLIT 8

// ---------------- device scratch ----------------
__device__ __half2 g_r2t2[NRET * BATCH / 2];   // LGN out, fp16 [n, b]
__device__ __half2 g_r3t2[NV1 * BATCH / 2];    // V1 out,  fp16 [n, b]
__device__ float   g_r4t[NIT * BATCH];         // IT out, fp32 [n, b]
__device__ float   g_sums[NRET + NV1 + NIT];
__device__ int     g_idx1[NV1 * MAX1];
__device__ int     g_cnt1[NV1];
__device__ int     g_idx2[NIT * MAX2];
__device__ int     g_cnt2[NIT];
__device__ float   g_part[KSPLIT * NCLSP * BATCH];

__device__ __forceinline__ float sigmoidf_(float z) {
    return 1.0f / (1.0f + __expf(-z));
}

__device__ __forceinline__ void ffma2(unsigned long long &d,
                                      unsigned long long a,
                                      unsigned long long b) {
    asm("fma.rn.f32x2 %0, %1, %2, %0;" : "+l"(d) : "l"(a), "l"(b));
}
__device__ __forceinline__ unsigned long long dup_f32(float w) {
    unsigned long long r;
    asm("mov.b64 %0, {%1, %1};" : "=l"(r) : "f"(w));
    return r;
}
__device__ __forceinline__ void unpack2(unsigned long long d, float &lo, float &hi) {
    asm("mov.b64 {%0, %1}, %2;" : "=f"(lo), "=f"(hi) : "l"(d));
}

// ---------------- kernel A: per-neuron weight sums ----------------
__global__ void sums_kernel(const float* __restrict__ w_lgn,
                            const float* __restrict__ w_v1,
                            const float* __restrict__ w_it,
                            float* __restrict__ sums) {
    int i = blockIdx.x * blockDim.x + threadIdx.x;
    if (i < NRET) {
        float s = 0.f;
        #pragma unroll
        for (int k = 0; k < 16; k++) s += w_lgn[i * 16 + k];
        sums[i] = s;
    } else if (i < NRET + NV1) {
        int j = i - NRET;
        float s = 0.f;
        #pragma unroll
        for (int k = 0; k < 32; k++) s += w_v1[j * 32 + k];
        sums[NRET + j] = s;
    } else if (i < NRET + NV1 + NIT) {
        int j = i - NRET - NV1;
        float s = 0.f;
        #pragma unroll
        for (int k = 0; k < 32; k++) s += w_it[j * 32 + k];
        sums[NRET + NV1 + j] = s;
    }
}

// ---------------- kernel B: retina + LGN fused, tiled, fp16 out ----------------
// block 256 = 8 warps. Tile: 32 n x 64 b. Warp = fixed b, 32 consecutive n.
// float4 gather when receptive field is contiguous+aligned (true for arange map);
// smem transpose for coalesced fp16 stores.
__global__ void retina_lgn_kernel(const float* __restrict__ x,
                                  const int* __restrict__ pm,
                                  const float* __restrict__ w_ret,
                                  const float* __restrict__ b_ret,
                                  const float* __restrict__ s_lgn,
                                  const float* __restrict__ b_lgn,
                                  __half* __restrict__ r2t) {
    __shared__ float s[32][65];
    int t = threadIdx.x;
    int n_loc = t & 31;
    int bw = t >> 5;                 // warp id: 8 b-groups
    int n = blockIdx.x * 32 + n_loc;
    int b_base = blockIdx.y * 64;

    int4 pp[4];
    float4 ww[4];
    const int4*   pm4 = (const int4*)(pm + n * 16);
    const float4* w4  = (const float4*)(w_ret + n * 16);
    bool cont[4];
    #pragma unroll
    for (int q = 0; q < 4; q++) {
        pp[q] = pm4[q];
        ww[q] = w4[q];
        cont[q] = (pp[q].y == pp[q].x + 1) && (pp[q].z == pp[q].x + 2) &&
                  (pp[q].w == pp[q].x + 3) && ((pp[q].x & 3) == 0);
    }
    float br = b_ret[n], sl = s_lgn[n], bl = b_lgn[n];

    #pragma unroll
    for (int p = 0; p < 8; p++) {
        int b_loc = bw * 8 + p;
        const float* xb = x + (long long)(b_base + b_loc) * NPIX;
        float acc = 0.f;
        #pragma unroll
        for (int q = 0; q < 4; q++) {
            if (cont[q]) {
                float4 xv = *(const float4*)(xb + pp[q].x);
                acc += xv.x * ww[q].x + xv.y * ww[q].y +
                       xv.z * ww[q].z + xv.w * ww[q].w;
            } else {
                acc += xb[pp[q].x] * ww[q].x + xb[pp[q].y] * ww[q].y +
                       xb[pp[q].z] * ww[q].z + xb[pp[q].w] * ww[q].w;
            }
        }
        float r1 = sigmoidf_(acc - br);
        s[n_loc][b_loc] = sigmoidf_(r1 * sl - bl);
    }
    __syncthreads();
    // coalesced fp16 writes: warp = one (n, 32-b half-row)
    int lane = t & 31;
    int w = t >> 5;
    #pragma unroll
    for (int i = 0; i < 8; i++) {
        int row = w + i * 8;         // 0..63
        int n_o = row >> 1;
        int b_o = (row & 1) * 32 + lane;
        float v = s[n_o][b_o];
        r2t[(long long)(blockIdx.x * 32 + n_o) * BATCH + b_base + b_o] =
            __float2half(v);
    }
}

// ---------------- kernel C: deterministic CSR build ----------------
__global__ void build_csr_kernel(const int* __restrict__ m, int rows, int cols,
                                 int maxnnz, int* __restrict__ idx,
                                 int* __restrict__ cnt) {
    int warp = (blockIdx.x * blockDim.x + threadIdx.x) >> 5;
    int lane = threadIdx.x & 31;
    if (warp >= rows) return;
    const int* row = m + (long long)warp * cols;
    int* out = idx + (long long)warp * maxnnz;
    int c = 0;
    for (int c0 = 0; c0 < cols; c0 += 32) {
        int v = row[c0 + lane];
        unsigned msk = __ballot_sync(0xffffffffu, v != 0);
        if (v) {
            int pos = c + __popc(msk & ((1u << lane) - 1));
            if (pos < maxnnz) out[pos] = c0 + lane;
        }
        c += __popc(msk);
    }
    if (lane == 0) cnt[warp] = (c < maxnnz) ? c : maxnnz;
}

// ---------------- kernel D1: sparse mean + sigmoid, fp16 -> fp16 ----------------
// block 128 threads, thread = 2 batch columns via half2.
__global__ void spmm_act_h2h(const int* __restrict__ idx,
                             const int* __restrict__ cnt, int maxnnz,
                             const __half2* __restrict__ src2,
                             const float* __restrict__ s,
                             const float* __restrict__ bias,
                             __half2* __restrict__ dst2) {
    int j = blockIdx.x;
    int b2 = threadIdx.x;            // 0..127
    int n = cnt[j];
    const int* ji = idx + (long long)j * maxnnz;
    float ax = 0.f, ay = 0.f;
    int k = 0;
    for (; k + 4 <= n; k += 4) {
        int i0 = ji[k], i1 = ji[k+1], i2 = ji[k+2], i3 = ji[k+3];
        float2 v0 = __half22float2(src2[i0 * (BATCH/2) + b2]);
        float2 v1 = __half22float2(src2[i1 * (BATCH/2) + b2]);
        float2 v2 = __half22float2(src2[i2 * (BATCH/2) + b2]);
        float2 v3 = __half22float2(src2[i3 * (BATCH/2) + b2]);
        ax += v0.x + v1.x + v2.x + v3.x;
        ay += v0.y + v1.y + v2.y + v3.y;
    }
    for (; k < n; k++) {
        float2 v = __half22float2(src2[ji[k] * (BATCH/2) + b2]);
        ax += v.x; ay += v.y;
    }
    float sj = s[j], bj = bias[j], fn = (float)n;
    float ox = sigmoidf_((ax / fn) * sj - bj);
    float oy = sigmoidf_((ay / fn) * sj - bj);
    dst2[(long long)j * (BATCH/2) + b2] = __floats2half2_rn(ox, oy);
}

// ---------------- kernel D2: sparse mean + sigmoid, fp16 -> fp32 ----------------
__global__ void spmm_act_h2f(const int* __restrict__ idx,
                             const int* __restrict__ cnt, int maxnnz,
                             const __half2* __restrict__ src2,
                             const float* __restrict__ s,
                             const float* __restrict__ bias,
                             float* __restrict__ dst) {
    int j = blockIdx.x;
    int b2 = threadIdx.x;
    int n = cnt[j];
    const int* ji = idx + (long long)j * maxnnz;
    float ax = 0.f, ay = 0.f;
    int k = 0;
    for (; k + 4 <= n; k += 4) {
        int i0 = ji[k], i1 = ji[k+1], i2 = ji[k+2], i3 = ji[k+3];
        float2 v0 = __half22float2(src2[i0 * (BATCH/2) + b2]);
        float2 v1 = __half22float2(src2[i1 * (BATCH/2) + b2]);
        float2 v2 = __half22float2(src2[i2 * (BATCH/2) + b2]);
        float2 v3 = __half22float2(src2[i3 * (BATCH/2) + b2]);
        ax += v0.x + v1.x + v2.x + v3.x;
        ay += v0.y + v1.y + v2.y + v3.y;
    }
    for (; k < n; k++) {
        float2 v = __half22float2(src2[ji[k] * (BATCH/2) + b2]);
        ax += v.x; ay += v.y;
    }
    float sj = s[j], bj = bias[j], fn = (float)n;
    float2 o;
    o.x = sigmoidf_((ax / fn) * sj - bj);
    o.y = sigmoidf_((ay / fn) * sj - bj);
    *(float2*)(dst + (long long)j * BATCH + 2 * b2) = o;
}

// ---------------- kernel E: classifier GEMM, split-K, packed f32x2 FMA ----------
// A = r4t [NK, BATCH] fp32, W = W_cls [NCLS, NK] fp32.
// Tile: 64 c x 128 b x 32 k, 256 threads, micro 4c x 8b (4 ull accs per c).
#define TC 64
#define TB 128
#define TKK 32
__global__ void cls_gemm_kernel(const float* __restrict__ A,
                                const float* __restrict__ W,
                                float* __restrict__ part) {
    __shared__ float As[TKK][TB];        // [k][b], rows 512B (16B-aligned)
    __shared__ float Ws[TKK][TC + 4];    // [k][c], rows 272B (16B-aligned)
    int tid = threadIdx.x;
    int c0 = blockIdx.x * TC;
    int b0 = blockIdx.y * TB;
    int ks = blockIdx.z;
    int kbase = ks * (NK / KSPLIT);
    int tx = tid & 15;                   // b group (8 b)
    int ty = tid >> 4;                   // c group (4 c)

    unsigned long long acc[4][4];
    #pragma unroll
    for (int i = 0; i < 4; i++)
        #pragma unroll
        for (int j = 0; j < 4; j++) acc[i][j] = 0ull;

    for (int kt = 0; kt < NK / KSPLIT; kt += TKK) {
        int k0 = kbase + kt;
        // A tile: 32k x 128b, 1024 float4s / 256 thr = 4 each (coalesced)
        #pragma unroll
        for (int i = 0; i < 4; i++) {
            int id = tid + i * 256;
            int r = id >> 5, c4 = id & 31;
            *(float4*)&As[r][c4 * 4] =
                *(const float4*)&A[(long long)(k0 + r) * BATCH + b0 + c4 * 4];
        }
        // W tile: 64c x 32k transposed into Ws[k][c]
        #pragma unroll
        for (int i = 0; i < 2; i++) {
            int id = tid + i * 256;
            int cr = id >> 3, kq = id & 7;
            int c = c0 + cr;
            float4 wv = make_float4(0.f, 0.f, 0.f, 0.f);
            if (c < NCLS)
                wv = *(const float4*)&W[(long long)c * NK + k0 + kq * 4];
            Ws[kq * 4 + 0][cr] = wv.x;
            Ws[kq * 4 + 1][cr] = wv.y;
            Ws[kq * 4 + 2][cr] = wv.z;
            Ws[kq * 4 + 3][cr] = wv.w;
        }
        __syncthreads();
        #pragma unroll
        for (int kk = 0; kk < TKK; kk++) {
            const ulonglong2* ap = (const ulonglong2*)&As[kk][tx * 8];
            ulonglong2 a01 = ap[0];
            ulonglong2 a23 = ap[1];
            float4 wv = *(const float4*)&Ws[kk][ty * 4];
            unsigned long long w0 = dup_f32(wv.x);
            unsigned long long w1 = dup_f32(wv.y);
            unsigned long long w2 = dup_f32(wv.z);
            unsigned long long w3 = dup_f32(wv.w);
            ffma2(acc[0][0], w0, a01.x); ffma2(acc[0][1], w0, a01.y);
            ffma2(acc[0][2], w0, a23.x); ffma2(acc[0][3], w0, a23.y);
            ffma2(acc[1][0], w1, a01.x); ffma2(acc[1][1], w1, a01.y);
            ffma2(acc[1][2], w1, a23.x); ffma2(acc[1][3], w1, a23.y);
            ffma2(acc[2][0], w2, a01.x); ffma2(acc[2][1], w2, a01.y);
            ffma2(acc[2][2], w2, a23.x); ffma2(acc[2][3], w2, a23.y);
            ffma2(acc[3][0], w3, a01.x); ffma2(acc[3][1], w3, a01.y);
            ffma2(acc[3][2], w3, a23.x); ffma2(acc[3][3], w3, a23.y);
        }
        __syncthreads();
    }
    // store partials: part[(ks*NCLSP + c) * BATCH + b], float2 contiguous in b
    #pragma unroll
    for (int i = 0; i < 4; i++) {
        int c = c0 + ty * 4 + i;
        float* pr = part + ((long long)ks * NCLSP + c) * BATCH + b0 + tx * 8;
        #pragma unroll
        for (int j = 0; j < 4; j++) {
            float2 f;
            unpack2(acc[i][j], f.x, f.y);
            *(float2*)(pr + 2 * j) = f;
        }
    }
}

// ---------------- kernel F: split-K reduce + bias ----------------
__global__ void reduce_kernel(const float* __restrict__ part,
                              const float* __restrict__ b_cls,
                              float* __restrict__ out) {
    int id = blockIdx.x * blockDim.x + threadIdx.x;
    int b = id & (BATCH - 1);
    int c = id >> 8;
    if (c >= NCLS) return;
    float acc = b_cls[c];
    #pragma unroll
    for (int ks = 0; ks < KSPLIT; ks++)
        acc += part[((long long)ks * NCLSP + c) * BATCH + b];
    out[(long long)b * NCLS + c] = acc;
}

// ---------------- launch ----------------
extern "C" void kernel_launch(void* const* d_in, const int* in_sizes, int n_in,
                              void* d_out, int out_size) {
    const float* x        = (const float*)d_in[0];
    const float* w_ret    = (const float*)d_in[1];
    const float* b_ret    = (const float*)d_in[2];
    const float* w_lgn    = (const float*)d_in[3];
    const float* b_lgn    = (const float*)d_in[4];
    const float* w_v1     = (const float*)d_in[5];
    const float* b_v1     = (const float*)d_in[6];
    const float* w_it     = (const float*)d_in[7];
    const float* b_it     = (const float*)d_in[8];
    const float* W_cls    = (const float*)d_in[9];
    const float* b_cls    = (const float*)d_in[10];
    const int*   pixel_map= (const int*)d_in[11];
    const int*   m1       = (const int*)d_in[12];
    const int*   m2       = (const int*)d_in[13];
    float* out = (float*)d_out;

    __half2* r2t2 = nullptr; __half2* r3t2 = nullptr; float* r4t = nullptr;
    float* sums = nullptr; float* partp = nullptr;
    int *idx1 = nullptr, *cnt1 = nullptr, *idx2 = nullptr, *cnt2 = nullptr;
    cudaGetSymbolAddress((void**)&r2t2, g_r2t2);
    cudaGetSymbolAddress((void**)&r3t2, g_r3t2);
    cudaGetSymbolAddress((void**)&r4t,  g_r4t);
    cudaGetSymbolAddress((void**)&sums, g_sums);
    cudaGetSymbolAddress((void**)&partp,g_part);
    cudaGetSymbolAddress((void**)&idx1, g_idx1);
    cudaGetSymbolAddress((void**)&cnt1, g_cnt1);
    cudaGetSymbolAddress((void**)&idx2, g_idx2);
    cudaGetSymbolAddress((void**)&cnt2, g_cnt2);

    // A: weight sums
    sums_kernel<<<(NRET + NV1 + NIT + 255) / 256, 256>>>(w_lgn, w_v1, w_it, sums);
    // C: CSR builds
    build_csr_kernel<<<(NV1 * 32 + 255) / 256, 256>>>(m1, NV1, NLGN, MAX1, idx1, cnt1);
    build_csr_kernel<<<(NIT * 32 + 255) / 256, 256>>>(m2, NIT, NV1, MAX2, idx2, cnt2);
    // B: retina + LGN (tiled)
    {
        dim3 grid(NRET / 32, BATCH / 64);
        retina_lgn_kernel<<<grid, 256>>>(x, pixel_map, w_ret, b_ret,
                                         sums, b_lgn, (__half*)r2t2);
    }
    // D1: V1 (fp16 -> fp16)
    spmm_act_h2h<<<NV1, BATCH / 2>>>(idx1, cnt1, MAX1, r2t2,
                                     sums + NRET, b_v1, r3t2);
    // D2: IT (fp16 -> fp32)
    spmm_act_h2f<<<NIT, BATCH / 2>>>(idx2, cnt2, MAX2, r3t2,
                                     sums + NRET + NV1, b_it, r4t);
    // E: classifier split-K GEMM (f32x2)
    {
        dim3 grid(NCLSP / TC, BATCH / TB, KSPLIT);
        cls_gemm_kernel<<<grid, 256>>>(r4t, W_cls, partp);
    }
    // F: reduce + bias
    reduce_kernel<<<(NCLSP * BATCH + 255) / 256, 256>>>(partp, b_cls, out);
    (void)in_sizes; (void)n_in; (void)out_size;
}

// round 7
// speedup vs baseline: 1.2375x; 1.0715x over previous
#include <cuda_runtime.h>
#include <cuda_fp16.h>
#include <cuda_bf16.h>

// ---------------- problem constants ----------------
#define BATCH  256
#define NPIX   49152
#define NRET   3072
#define NLGN   3072
#define NV1    6144
#define NIT    3072
#define NCLS   1000
#define NCLSP  1024
#define NK     NIT

#define MAX1   128
#define MAX2   256
#define KSPLIT 16

// phase-1 block roles
#define RET_BX   96                  // NRET/32
#define RET_BY   8                   // BATCH/32
#define RET_BLKS (RET_BX * RET_BY)   // 768
#define CSR1_BLKS (NV1 / 8)          // 768 (8 rows/block)
#define CSR2_BLKS (NIT / 8)          // 384
#define SUMS_BLKS ((NRET + NV1 + NIT + 255) / 256)  // 48

// ---------------- device scratch ----------------
__device__ __half2 g_r2t2[NRET * BATCH / 2];
__device__ __half2 g_r3t2[NV1 * BATCH / 2];
__device__ float   g_r4t[NIT * BATCH];
__device__ float   g_sums[NRET + NV1 + NIT];
__device__ int     g_idx1[NV1 * MAX1];
__device__ int     g_cnt1[NV1];
__device__ int     g_idx2[NIT * MAX2];
__device__ int     g_cnt2[NIT];
__device__ float   g_part[KSPLIT * NCLSP * BATCH];

__device__ __forceinline__ float sigmoidf_(float z) {
    return 1.0f / (1.0f + __expf(-z));
}
__device__ __forceinline__ void ffma2(unsigned long long &d,
                                      unsigned long long a,
                                      unsigned long long b) {
    asm("fma.rn.f32x2 %0, %1, %2, %0;" : "+l"(d) : "l"(a), "l"(b));
}
__device__ __forceinline__ unsigned long long dup_f32(float w) {
    unsigned long long r;
    asm("mov.b64 %0, {%1, %1};" : "=l"(r) : "f"(w));
    return r;
}
__device__ __forceinline__ void unpack2(unsigned long long d, float &lo, float &hi) {
    asm("mov.b64 {%0, %1}, %2;" : "=f"(lo), "=f"(hi) : "l"(d));
}

// ---------------- phase-1 role: CSR build (warp per row, int4 loads) ----------
__device__ __forceinline__ void csr_row(const int* __restrict__ m, int cols,
                                        int maxnnz, int* __restrict__ idx,
                                        int* __restrict__ cnt, int row, int lane) {
    const int4* row4 = (const int4*)(m + (long long)row * cols);
    int* out = idx + (long long)row * maxnnz;
    unsigned lt = (1u << lane) - 1;
    int c = 0;
    int iters = cols >> 7;              // 128 cols per iteration
    for (int it = 0; it < iters; it++) {
        int4 v = row4[it * 32 + lane];
        int cbase = it * 128 + 4 * lane;
        #pragma unroll
        for (int e = 0; e < 4; e++) {
            int val = (e == 0) ? v.x : (e == 1) ? v.y : (e == 2) ? v.z : v.w;
            unsigned msk = __ballot_sync(0xffffffffu, val != 0);
            if (val) {
                int pos = c + __popc(msk & lt);
                if (pos < maxnnz) out[pos] = cbase + e;
            }
            c += __popc(msk);
        }
    }
    if (lane == 0) cnt[row] = (c < maxnnz) ? c : maxnnz;
}

// ---------------- phase-1 mega-kernel ----------------
__global__ void phase1_kernel(const float* __restrict__ x,
                              const int* __restrict__ pm,
                              const float* __restrict__ w_ret,
                              const float* __restrict__ b_ret,
                              const float* __restrict__ w_lgn,
                              const float* __restrict__ b_lgn,
                              const float* __restrict__ w_v1,
                              const float* __restrict__ w_it,
                              const int* __restrict__ m1,
                              const int* __restrict__ m2,
                              __half* __restrict__ r2t,
                              float* __restrict__ sums,
                              int* __restrict__ idx1, int* __restrict__ cnt1,
                              int* __restrict__ idx2, int* __restrict__ cnt2) {
    int blk = blockIdx.x;
    int t = threadIdx.x;
    int lane = t & 31;
    int w = t >> 5;

    if (blk < RET_BLKS) {
        // -------- retina + LGN: tile 32n x 32b, thread = 1n x 4b --------
        __shared__ float s[32][33];
        int bn = blk % RET_BX;
        int bb = blk / RET_BX;
        int n = bn * 32 + lane;
        int b0 = bb * 32 + w * 4;
        int base = n * 16;

        const int4*   pm4 = (const int4*)(pm + base);
        const float4* w4  = (const float4*)(w_ret + base);
        float4 ww[4];
        int4 pp[4];
        bool fast = true;
        #pragma unroll
        for (int q = 0; q < 4; q++) {
            pp[q] = pm4[q];
            ww[q] = w4[q];
            int e = base + 4 * q;
            fast = fast && (pp[q].x == e) && (pp[q].y == e + 1) &&
                   (pp[q].z == e + 2) && (pp[q].w == e + 3);
        }
        float acc[4] = {0.f, 0.f, 0.f, 0.f};
        if (fast) {
            #pragma unroll
            for (int p = 0; p < 4; p++) {
                const float4* xp = (const float4*)(x + (long long)(b0 + p) * NPIX + base);
                #pragma unroll
                for (int q = 0; q < 4; q++) {
                    float4 xv = xp[q];
                    acc[p] += xv.x * ww[q].x + xv.y * ww[q].y +
                              xv.z * ww[q].z + xv.w * ww[q].w;
                }
            }
        } else {
            #pragma unroll
            for (int p = 0; p < 4; p++) {
                const float* xb = x + (long long)(b0 + p) * NPIX;
                #pragma unroll
                for (int q = 0; q < 4; q++) {
                    acc[p] += xb[pp[q].x] * ww[q].x + xb[pp[q].y] * ww[q].y +
                              xb[pp[q].z] * ww[q].z + xb[pp[q].w] * ww[q].w;
                }
            }
        }
        float br = b_ret[n];
        // s_lgn computed inline (16 floats)
        float sl = 0.f;
        {
            const float4* wl = (const float4*)(w_lgn + base);
            #pragma unroll
            for (int q = 0; q < 4; q++) {
                float4 v = wl[q];
                sl += v.x + v.y + v.z + v.w;
            }
        }
        float bl = b_lgn[n];
        #pragma unroll
        for (int p = 0; p < 4; p++) {
            float r1 = sigmoidf_(acc[p] - br);
            s[lane][w * 4 + p] = sigmoidf_(r1 * sl - bl);
        }
        __syncthreads();
        #pragma unroll
        for (int i = 0; i < 4; i++) {
            int id = t + i * 256;
            int n_o = id >> 5, b_o = id & 31;
            r2t[(long long)(bn * 32 + n_o) * BATCH + bb * 32 + b_o] =
                __float2half(s[n_o][b_o]);
        }
        return;
    }
    blk -= RET_BLKS;
    if (blk < CSR1_BLKS) {
        int row = blk * 8 + w;
        csr_row(m1, NLGN, MAX1, idx1, cnt1, row, lane);
        return;
    }
    blk -= CSR1_BLKS;
    if (blk < CSR2_BLKS) {
        int row = blk * 8 + w;
        csr_row(m2, NV1, MAX2, idx2, cnt2, row, lane);
        return;
    }
    blk -= CSR2_BLKS;
    {
        int i = blk * 256 + t;
        if (i < NRET) {
            float s2 = 0.f;
            #pragma unroll
            for (int k = 0; k < 16; k++) s2 += w_lgn[i * 16 + k];
            sums[i] = s2;
        } else if (i < NRET + NV1) {
            int j = i - NRET;
            float s2 = 0.f;
            #pragma unroll
            for (int k = 0; k < 32; k++) s2 += w_v1[j * 32 + k];
            sums[NRET + j] = s2;
        } else if (i < NRET + NV1 + NIT) {
            int j = i - NRET - NV1;
            float s2 = 0.f;
            #pragma unroll
            for (int k = 0; k < 32; k++) s2 += w_it[j * 32 + k];
            sums[NRET + NV1 + j] = s2;
        }
    }
}

// ---------------- SpMM: 2 rows per block, unroll 8 ----------------
__global__ void spmm_act_h2h(const int* __restrict__ idx,
                             const int* __restrict__ cnt, int maxnnz,
                             const __half2* __restrict__ src2,
                             const float* __restrict__ s,
                             const float* __restrict__ bias,
                             __half2* __restrict__ dst2) {
    int j = blockIdx.x * 2 + (threadIdx.x >> 7);
    int b2 = threadIdx.x & 127;
    int n = cnt[j];
    const int* ji = idx + (long long)j * maxnnz;
    float ax = 0.f, ay = 0.f, cx = 0.f, cy = 0.f;
    int k = 0;
    for (; k + 8 <= n; k += 8) {
        float2 v0 = __half22float2(src2[ji[k+0] * (BATCH/2) + b2]);
        float2 v1 = __half22float2(src2[ji[k+1] * (BATCH/2) + b2]);
        float2 v2 = __half22float2(src2[ji[k+2] * (BATCH/2) + b2]);
        float2 v3 = __half22float2(src2[ji[k+3] * (BATCH/2) + b2]);
        float2 v4 = __half22float2(src2[ji[k+4] * (BATCH/2) + b2]);
        float2 v5 = __half22float2(src2[ji[k+5] * (BATCH/2) + b2]);
        float2 v6 = __half22float2(src2[ji[k+6] * (BATCH/2) + b2]);
        float2 v7 = __half22float2(src2[ji[k+7] * (BATCH/2) + b2]);
        ax += (v0.x + v1.x) + (v2.x + v3.x);
        ay += (v0.y + v1.y) + (v2.y + v3.y);
        cx += (v4.x + v5.x) + (v6.x + v7.x);
        cy += (v4.y + v5.y) + (v6.y + v7.y);
    }
    for (; k < n; k++) {
        float2 v = __half22float2(src2[ji[k] * (BATCH/2) + b2]);
        ax += v.x; ay += v.y;
    }
    ax += cx; ay += cy;
    float sj = s[j], bj = bias[j], fn = (float)n;
    float ox = sigmoidf_((ax / fn) * sj - bj);
    float oy = sigmoidf_((ay / fn) * sj - bj);
    dst2[(long long)j * (BATCH/2) + b2] = __floats2half2_rn(ox, oy);
}

__global__ void spmm_act_h2f(const int* __restrict__ idx,
                             const int* __restrict__ cnt, int maxnnz,
                             const __half2* __restrict__ src2,
                             const float* __restrict__ s,
                             const float* __restrict__ bias,
                             float* __restrict__ dst) {
    int j = blockIdx.x * 2 + (threadIdx.x >> 7);
    int b2 = threadIdx.x & 127;
    int n = cnt[j];
    const int* ji = idx + (long long)j * maxnnz;
    float ax = 0.f, ay = 0.f, cx = 0.f, cy = 0.f;
    int k = 0;
    for (; k + 8 <= n; k += 8) {
        float2 v0 = __half22float2(src2[ji[k+0] * (BATCH/2) + b2]);
        float2 v1 = __half22float2(src2[ji[k+1] * (BATCH/2) + b2]);
        float2 v2 = __half22float2(src2[ji[k+2] * (BATCH/2) + b2]);
        float2 v3 = __half22float2(src2[ji[k+3] * (BATCH/2) + b2]);
        float2 v4 = __half22float2(src2[ji[k+4] * (BATCH/2) + b2]);
        float2 v5 = __half22float2(src2[ji[k+5] * (BATCH/2) + b2]);
        float2 v6 = __half22float2(src2[ji[k+6] * (BATCH/2) + b2]);
        float2 v7 = __half22float2(src2[ji[k+7] * (BATCH/2) + b2]);
        ax += (v0.x + v1.x) + (v2.x + v3.x);
        ay += (v0.y + v1.y) + (v2.y + v3.y);
        cx += (v4.x + v5.x) + (v6.x + v7.x);
        cy += (v4.y + v5.y) + (v6.y + v7.y);
    }
    for (; k < n; k++) {
        float2 v = __half22float2(src2[ji[k] * (BATCH/2) + b2]);
        ax += v.x; ay += v.y;
    }
    ax += cx; ay += cy;
    float sj = s[j], bj = bias[j], fn = (float)n;
    float2 o;
    o.x = sigmoidf_((ax / fn) * sj - bj);
    o.y = sigmoidf_((ay / fn) * sj - bj);
    *(float2*)(dst + (long long)j * BATCH + 2 * b2) = o;
}

// ---------------- classifier GEMM, split-K=16, packed f32x2 ----------------
#define TC 64
#define TB 128
#define TKK 32
__global__ void cls_gemm_kernel(const float* __restrict__ A,
                                const float* __restrict__ W,
                                float* __restrict__ part) {
    __shared__ float As[TKK][TB];
    __shared__ float Ws[TKK][TC + 4];
    int tid = threadIdx.x;
    int c0 = blockIdx.x * TC;
    int b0 = blockIdx.y * TB;
    int ks = blockIdx.z;
    int kbase = ks * (NK / KSPLIT);
    int tx = tid & 15;
    int ty = tid >> 4;

    unsigned long long acc[4][4];
    #pragma unroll
    for (int i = 0; i < 4; i++)
        #pragma unroll
        for (int j = 0; j < 4; j++) acc[i][j] = 0ull;

    for (int kt = 0; kt < NK / KSPLIT; kt += TKK) {
        int k0 = kbase + kt;
        #pragma unroll
        for (int i = 0; i < 4; i++) {
            int id = tid + i * 256;
            int r = id >> 5, c4 = id & 31;
            *(float4*)&As[r][c4 * 4] =
                *(const float4*)&A[(long long)(k0 + r) * BATCH + b0 + c4 * 4];
        }
        #pragma unroll
        for (int i = 0; i < 2; i++) {
            int id = tid + i * 256;
            int cr = id >> 3, kq = id & 7;
            int c = c0 + cr;
            float4 wv = make_float4(0.f, 0.f, 0.f, 0.f);
            if (c < NCLS)
                wv = *(const float4*)&W[(long long)c * NK + k0 + kq * 4];
            Ws[kq * 4 + 0][cr] = wv.x;
            Ws[kq * 4 + 1][cr] = wv.y;
            Ws[kq * 4 + 2][cr] = wv.z;
            Ws[kq * 4 + 3][cr] = wv.w;
        }
        __syncthreads();
        #pragma unroll
        for (int kk = 0; kk < TKK; kk++) {
            const ulonglong2* ap = (const ulonglong2*)&As[kk][tx * 8];
            ulonglong2 a01 = ap[0];
            ulonglong2 a23 = ap[1];
            float4 wv = *(const float4*)&Ws[kk][ty * 4];
            unsigned long long w0 = dup_f32(wv.x);
            unsigned long long w1 = dup_f32(wv.y);
            unsigned long long w2 = dup_f32(wv.z);
            unsigned long long w3 = dup_f32(wv.w);
            ffma2(acc[0][0], w0, a01.x); ffma2(acc[0][1], w0, a01.y);
            ffma2(acc[0][2], w0, a23.x); ffma2(acc[0][3], w0, a23.y);
            ffma2(acc[1][0], w1, a01.x); ffma2(acc[1][1], w1, a01.y);
            ffma2(acc[1][2], w1, a23.x); ffma2(acc[1][3], w1, a23.y);
            ffma2(acc[2][0], w2, a01.x); ffma2(acc[2][1], w2, a01.y);
            ffma2(acc[2][2], w2, a23.x); ffma2(acc[2][3], w2, a23.y);
            ffma2(acc[3][0], w3, a01.x); ffma2(acc[3][1], w3, a01.y);
            ffma2(acc[3][2], w3, a23.x); ffma2(acc[3][3], w3, a23.y);
        }
        __syncthreads();
    }
    #pragma unroll
    for (int i = 0; i < 4; i++) {
        int c = c0 + ty * 4 + i;
        float* pr = part + ((long long)ks * NCLSP + c) * BATCH + b0 + tx * 8;
        #pragma unroll
        for (int j = 0; j < 4; j++) {
            float2 f;
            unpack2(acc[i][j], f.x, f.y);
            *(float2*)(pr + 2 * j) = f;
        }
    }
}

// ---------------- split-K reduce + bias ----------------
__global__ void reduce_kernel(const float* __restrict__ part,
                              const float* __restrict__ b_cls,
                              float* __restrict__ out) {
    int id = blockIdx.x * blockDim.x + threadIdx.x;
    int b = id & (BATCH - 1);
    int c = id >> 8;
    if (c >= NCLS) return;
    float acc = b_cls[c];
    #pragma unroll
    for (int ks = 0; ks < KSPLIT; ks++)
        acc += part[((long long)ks * NCLSP + c) * BATCH + b];
    out[(long long)b * NCLS + c] = acc;
}

// ---------------- launch ----------------
extern "C" void kernel_launch(void* const* d_in, const int* in_sizes, int n_in,
                              void* d_out, int out_size) {
    const float* x        = (const float*)d_in[0];
    const float* w_ret    = (const float*)d_in[1];
    const float* b_ret    = (const float*)d_in[2];
    const float* w_lgn    = (const float*)d_in[3];
    const float* b_lgn    = (const float*)d_in[4];
    const float* w_v1     = (const float*)d_in[5];
    const float* b_v1     = (const float*)d_in[6];
    const float* w_it     = (const float*)d_in[7];
    const float* b_it     = (const float*)d_in[8];
    const float* W_cls    = (const float*)d_in[9];
    const float* b_cls    = (const float*)d_in[10];
    const int*   pixel_map= (const int*)d_in[11];
    const int*   m1       = (const int*)d_in[12];
    const int*   m2       = (const int*)d_in[13];
    float* out = (float*)d_out;

    __half2* r2t2 = nullptr; __half2* r3t2 = nullptr; float* r4t = nullptr;
    float* sums = nullptr; float* partp = nullptr;
    int *idx1 = nullptr, *cnt1 = nullptr, *idx2 = nullptr, *cnt2 = nullptr;
    cudaGetSymbolAddress((void**)&r2t2, g_r2t2);
    cudaGetSymbolAddress((void**)&r3t2, g_r3t2);
    cudaGetSymbolAddress((void**)&r4t,  g_r4t);
    cudaGetSymbolAddress((void**)&sums, g_sums);
    cudaGetSymbolAddress((void**)&partp,g_part);
    cudaGetSymbolAddress((void**)&idx1, g_idx1);
    cudaGetSymbolAddress((void**)&cnt1, g_cnt1);
    cudaGetSymbolAddress((void**)&idx2, g_idx2);
    cudaGetSymbolAddress((void**)&cnt2, g_cnt2);

    // phase 1: retina+LGN, CSR builds, weight sums — one launch, full overlap
    {
        int nblk = RET_BLKS + CSR1_BLKS + CSR2_BLKS + SUMS_BLKS;
        phase1_kernel<<<nblk, 256>>>(x, pixel_map, w_ret, b_ret, w_lgn, b_lgn,
                                     w_v1, w_it, m1, m2, (__half*)r2t2, sums,
                                     idx1, cnt1, idx2, cnt2);
    }
    // V1
    spmm_act_h2h<<<NV1 / 2, 256>>>(idx1, cnt1, MAX1, r2t2,
                                   sums + NRET, b_v1, r3t2);
    // IT
    spmm_act_h2f<<<NIT / 2, 256>>>(idx2, cnt2, MAX2, r3t2,
                                   sums + NRET + NV1, b_it, r4t);
    // classifier
    {
        dim3 grid(NCLSP / TC, BATCH / TB, KSPLIT);
        cls_gemm_kernel<<<grid, 256>>>(r4t, W_cls, partp);
    }
    reduce_kernel<<<(NCLSP * BATCH + 255) / 256, 256>>>(partp, b_cls, out);
    (void)in_sizes; (void)n_in; (void)out_size;
}

// round 12
// speedup vs baseline: 1.7060x; 1.3786x over previous
#include <cuda_runtime.h>
#include <cuda_fp16.h>
#include <cuda_bf16.h>
#include <cstdint>

// ---------------- problem constants ----------------
#define BATCH  256
#define NPIX   49152
#define NRET   3072
#define NLGN   3072
#define NV1    6144
#define NIT    3072
#define NCLS   1000
#define NCLSP  1024
#define NK     NIT

#define MAX1   128
#define MAX2   256
#define KSPLIT 8

// phase-1 block roles
#define RET_BX   96
#define RET_BY   8
#define RET_BLKS (RET_BX * RET_BY)       // 768
#define CSR1_BLKS (NV1 / 8)              // 768
#define CSR2_BLKS (NIT / 8)              // 384
#define SUMS_BLKS ((NRET + NV1 + NIT + 255) / 256)  // 48
#define WPREP_BLKS (NCLSP / 4)           // 256

// ---------------- device scratch ----------------
__device__ __half2       g_r2t2[NRET * BATCH / 2];
__device__ __half2       g_r3t2[NV1 * BATCH / 2];
__device__ float         g_r4t[NIT * BATCH];          // [k, b] fp32
__device__ float         g_sums[NRET + NV1 + NIT];
__device__ int           g_idx1[NV1 * MAX1];
__device__ int           g_cnt1[NV1];
__device__ int           g_idx2[NIT * MAX2];
__device__ int           g_cnt2[NIT];
__device__ float         g_part[KSPLIT * NCLSP * BATCH];
__device__ __nv_bfloat16 g_whi[NCLSP * NK];           // W hi, [c, k]
__device__ __nv_bfloat16 g_wlo[NCLSP * NK];           // W lo
__device__ __nv_bfloat16 g_ahi[BATCH * NK];           // acts hi, [b, k]
__device__ __nv_bfloat16 g_alo[BATCH * NK];           // acts lo

__device__ __forceinline__ float sigmoidf_(float z) {
    return 1.0f / (1.0f + __expf(-z));
}

// ---------------- warp MMA: m16n8k16 bf16 (sm_80+ baseline feature) --------
__device__ __forceinline__ void mma16816(float* c, const uint32_t* a,
                                         const uint32_t* b) {
    asm volatile(
        "mma.sync.aligned.m16n8k16.row.col.f32.bf16.bf16.f32 "
        "{%0,%1,%2,%3}, {%4,%5,%6,%7}, {%8,%9}, {%0,%1,%2,%3};"
        : "+f"(c[0]), "+f"(c[1]), "+f"(c[2]), "+f"(c[3])
        : "r"(a[0]), "r"(a[1]), "r"(a[2]), "r"(a[3]),
          "r"(b[0]), "r"(b[1]));
}

// ---------------- phase-1 role: CSR build ----------------
__device__ __forceinline__ void csr_row(const int* __restrict__ m, int cols,
                                        int maxnnz, int* __restrict__ idx,
                                        int* __restrict__ cnt, int row, int lane) {
    const int4* row4 = (const int4*)(m + (long long)row * cols);
    int* out = idx + (long long)row * maxnnz;
    unsigned lt = (1u << lane) - 1;
    int c = 0;
    int iters = cols >> 7;
    for (int it = 0; it < iters; it++) {
        int4 v = row4[it * 32 + lane];
        int cbase = it * 128 + 4 * lane;
        #pragma unroll
        for (int e = 0; e < 4; e++) {
            int val = (e == 0) ? v.x : (e == 1) ? v.y : (e == 2) ? v.z : v.w;
            unsigned msk = __ballot_sync(0xffffffffu, val != 0);
            if (val) {
                int pos = c + __popc(msk & lt);
                if (pos < maxnnz) out[pos] = cbase + e;
            }
            c += __popc(msk);
        }
    }
    if (lane == 0) cnt[row] = (c < maxnnz) ? c : maxnnz;
}

// ---------------- phase-1 mega-kernel ----------------
__global__ void phase1_kernel(const float* __restrict__ x,
                              const int* __restrict__ pm,
                              const float* __restrict__ w_ret,
                              const float* __restrict__ b_ret,
                              const float* __restrict__ w_lgn,
                              const float* __restrict__ b_lgn,
                              const float* __restrict__ w_v1,
                              const float* __restrict__ w_it,
                              const float* __restrict__ W_cls,
                              const int* __restrict__ m1,
                              const int* __restrict__ m2,
                              __half* __restrict__ r2t,
                              float* __restrict__ sums,
                              int* __restrict__ idx1, int* __restrict__ cnt1,
                              int* __restrict__ idx2, int* __restrict__ cnt2,
                              __nv_bfloat16* __restrict__ whi,
                              __nv_bfloat16* __restrict__ wlo) {
    int blk = blockIdx.x;
    int t = threadIdx.x;
    int lane = t & 31;
    int w = t >> 5;

    if (blk < RET_BLKS) {
        __shared__ float s[32][33];
        int bn = blk % RET_BX;
        int bb = blk / RET_BX;
        int n = bn * 32 + lane;
        int b0 = bb * 32 + w * 4;
        int base = n * 16;

        const int4*   pm4 = (const int4*)(pm + base);
        const float4* w4  = (const float4*)(w_ret + base);
        float4 ww[4];
        int4 pp[4];
        bool fast = true;
        #pragma unroll
        for (int q = 0; q < 4; q++) {
            pp[q] = pm4[q];
            ww[q] = w4[q];
            int e = base + 4 * q;
            fast = fast && (pp[q].x == e) && (pp[q].y == e + 1) &&
                   (pp[q].z == e + 2) && (pp[q].w == e + 3);
        }
        float acc[4] = {0.f, 0.f, 0.f, 0.f};
        if (fast) {
            #pragma unroll
            for (int p = 0; p < 4; p++) {
                const float4* xp = (const float4*)(x + (long long)(b0 + p) * NPIX + base);
                #pragma unroll
                for (int q = 0; q < 4; q++) {
                    float4 xv = xp[q];
                    acc[p] += xv.x * ww[q].x + xv.y * ww[q].y +
                              xv.z * ww[q].z + xv.w * ww[q].w;
                }
            }
        } else {
            #pragma unroll
            for (int p = 0; p < 4; p++) {
                const float* xb = x + (long long)(b0 + p) * NPIX;
                #pragma unroll
                for (int q = 0; q < 4; q++) {
                    acc[p] += xb[pp[q].x] * ww[q].x + xb[pp[q].y] * ww[q].y +
                              xb[pp[q].z] * ww[q].z + xb[pp[q].w] * ww[q].w;
                }
            }
        }
        float br = b_ret[n];
        float sl = 0.f;
        {
            const float4* wl = (const float4*)(w_lgn + base);
            #pragma unroll
            for (int q = 0; q < 4; q++) {
                float4 v = wl[q];
                sl += v.x + v.y + v.z + v.w;
            }
        }
        float bl = b_lgn[n];
        #pragma unroll
        for (int p = 0; p < 4; p++) {
            float r1 = sigmoidf_(acc[p] - br);
            s[lane][w * 4 + p] = sigmoidf_(r1 * sl - bl);
        }
        __syncthreads();
        #pragma unroll
        for (int i = 0; i < 4; i++) {
            int id = t + i * 256;
            int n_o = id >> 5, b_o = id & 31;
            r2t[(long long)(bn * 32 + n_o) * BATCH + bb * 32 + b_o] =
                __float2half(s[n_o][b_o]);
        }
        return;
    }
    blk -= RET_BLKS;
    if (blk < CSR1_BLKS) {
        csr_row(m1, NLGN, MAX1, idx1, cnt1, blk * 8 + w, lane);
        return;
    }
    blk -= CSR1_BLKS;
    if (blk < CSR2_BLKS) {
        csr_row(m2, NV1, MAX2, idx2, cnt2, blk * 8 + w, lane);
        return;
    }
    blk -= CSR2_BLKS;
    if (blk < SUMS_BLKS) {
        int i = blk * 256 + t;
        if (i < NRET) {
            float s2 = 0.f;
            #pragma unroll
            for (int k = 0; k < 16; k++) s2 += w_lgn[i * 16 + k];
            sums[i] = s2;
        } else if (i < NRET + NV1) {
            int j = i - NRET;
            float s2 = 0.f;
            #pragma unroll
            for (int k = 0; k < 32; k++) s2 += w_v1[j * 32 + k];
            sums[NRET + j] = s2;
        } else if (i < NRET + NV1 + NIT) {
            int j = i - NRET - NV1;
            float s2 = 0.f;
            #pragma unroll
            for (int k = 0; k < 32; k++) s2 += w_it[j * 32 + k];
            sums[NRET + NV1 + j] = s2;
        }
        return;
    }
    blk -= SUMS_BLKS;
    {
        // W_cls bf16 hi/lo split, rows >= NCLS zero-padded
        int row0 = blk * 4;
        #pragma unroll
        for (int rr = 0; rr < 4; rr++) {
            int r = row0 + rr;
            long long rb = (long long)r * NK;
            #pragma unroll
            for (int i = 0; i < NK / 256; i++) {
                int col = i * 256 + t;
                float v = (r < NCLS) ? W_cls[rb + col] : 0.f;
                __nv_bfloat16 hi = __float2bfloat16(v);
                __nv_bfloat16 lo = __float2bfloat16(v - __bfloat162float(hi));
                whi[rb + col] = hi;
                wlo[rb + col] = lo;
            }
        }
    }
}

// ---------------- SpMM kernels ----------------
__global__ void spmm_act_h2h(const int* __restrict__ idx,
                             const int* __restrict__ cnt, int maxnnz,
                             const __half2* __restrict__ src2,
                             const float* __restrict__ s,
                             const float* __restrict__ bias,
                             __half2* __restrict__ dst2) {
    int j = blockIdx.x * 2 + (threadIdx.x >> 7);
    int b2 = threadIdx.x & 127;
    int n = cnt[j];
    const int* ji = idx + (long long)j * maxnnz;
    float ax = 0.f, ay = 0.f, cx = 0.f, cy = 0.f;
    int k = 0;
    for (; k + 8 <= n; k += 8) {
        float2 v0 = __half22float2(src2[ji[k+0] * (BATCH/2) + b2]);
        float2 v1 = __half22float2(src2[ji[k+1] * (BATCH/2) + b2]);
        float2 v2 = __half22float2(src2[ji[k+2] * (BATCH/2) + b2]);
        float2 v3 = __half22float2(src2[ji[k+3] * (BATCH/2) + b2]);
        float2 v4 = __half22float2(src2[ji[k+4] * (BATCH/2) + b2]);
        float2 v5 = __half22float2(src2[ji[k+5] * (BATCH/2) + b2]);
        float2 v6 = __half22float2(src2[ji[k+6] * (BATCH/2) + b2]);
        float2 v7 = __half22float2(src2[ji[k+7] * (BATCH/2) + b2]);
        ax += (v0.x + v1.x) + (v2.x + v3.x);
        ay += (v0.y + v1.y) + (v2.y + v3.y);
        cx += (v4.x + v5.x) + (v6.x + v7.x);
        cy += (v4.y + v5.y) + (v6.y + v7.y);
    }
    for (; k < n; k++) {
        float2 v = __half22float2(src2[ji[k] * (BATCH/2) + b2]);
        ax += v.x; ay += v.y;
    }
    ax += cx; ay += cy;
    float sj = s[j], bj = bias[j], fn = (float)n;
    float ox = sigmoidf_((ax / fn) * sj - bj);
    float oy = sigmoidf_((ay / fn) * sj - bj);
    dst2[(long long)j * (BATCH/2) + b2] = __floats2half2_rn(ox, oy);
}

__global__ void spmm_act_h2f(const int* __restrict__ idx,
                             const int* __restrict__ cnt, int maxnnz,
                             const __half2* __restrict__ src2,
                             const float* __restrict__ s,
                             const float* __restrict__ bias,
                             float* __restrict__ dst) {
    int j = blockIdx.x * 2 + (threadIdx.x >> 7);
    int b2 = threadIdx.x & 127;
    int n = cnt[j];
    const int* ji = idx + (long long)j * maxnnz;
    float ax = 0.f, ay = 0.f, cx = 0.f, cy = 0.f;
    int k = 0;
    for (; k + 8 <= n; k += 8) {
        float2 v0 = __half22float2(src2[ji[k+0] * (BATCH/2) + b2]);
        float2 v1 = __half22float2(src2[ji[k+1] * (BATCH/2) + b2]);
        float2 v2 = __half22float2(src2[ji[k+2] * (BATCH/2) + b2]);
        float2 v3 = __half22float2(src2[ji[k+3] * (BATCH/2) + b2]);
        float2 v4 = __half22float2(src2[ji[k+4] * (BATCH/2) + b2]);
        float2 v5 = __half22float2(src2[ji[k+5] * (BATCH/2) + b2]);
        float2 v6 = __half22float2(src2[ji[k+6] * (BATCH/2) + b2]);
        float2 v7 = __half22float2(src2[ji[k+7] * (BATCH/2) + b2]);
        ax += (v0.x + v1.x) + (v2.x + v3.x);
        ay += (v0.y + v1.y) + (v2.y + v3.y);
        cx += (v4.x + v5.x) + (v6.x + v7.x);
        cy += (v4.y + v5.y) + (v6.y + v7.y);
    }
    for (; k < n; k++) {
        float2 v = __half22float2(src2[ji[k] * (BATCH/2) + b2]);
        ax += v.x; ay += v.y;
    }
    ax += cx; ay += cy;
    float sj = s[j], bj = bias[j], fn = (float)n;
    float2 o;
    o.x = sigmoidf_((ax / fn) * sj - bj);
    o.y = sigmoidf_((ay / fn) * sj - bj);
    *(float2*)(dst + (long long)j * BATCH + 2 * b2) = o;
}

// ---------------- acts transpose + bf16 hi/lo split ----------------
__global__ void prep_acts_kernel(const float* __restrict__ r4t,
                                 __nv_bfloat16* __restrict__ ahi,
                                 __nv_bfloat16* __restrict__ alo) {
    __shared__ float s[32][33];
    int t = threadIdx.x;
    int k0 = blockIdx.x * 32;
    int b0 = blockIdx.y * 32;
    #pragma unroll
    for (int i = 0; i < 4; i++) {
        int u = t + i * 256;
        s[u >> 5][u & 31] = r4t[(long long)(k0 + (u >> 5)) * BATCH + b0 + (u & 31)];
    }
    __syncthreads();
    int b_loc = t >> 3;
    int kq = (t & 7) * 4;
    long long base = (long long)(b0 + b_loc) * NK + k0 + kq;
    #pragma unroll
    for (int j2 = 0; j2 < 4; j2++) {
        float v = s[kq + j2][b_loc];
        __nv_bfloat16 hi = __float2bfloat16(v);
        __nv_bfloat16 lo = __float2bfloat16(v - __bfloat162float(hi));
        ahi[base + j2] = hi;
        alo[base + j2] = lo;
    }
}

// ---------------- classifier GEMM via mma.sync (bf16 3-split) --------------
// part[ks][c][b] += W[c,k] * A[b,k]^T over this split's k-range.
// CTA tile 128c x 64b, k-chunk 32, 8 warps (4c x 2b), warp tile 32c x 32b.
#define KCH       (NK / KSPLIT / 32)     // 12 chunks per CTA
#define SROW      80                     // smem row stride (bytes), conflict-free
#define WHI_OFF   0
#define WLO_OFF   (128 * SROW)           // 10240
#define AHI_OFF   (2 * 128 * SROW)       // 20480
#define ALO_OFF   (AHI_OFF + 64 * SROW)  // 25600
#define STAGE2_B  (ALO_OFF + 64 * SROW)  // 30720
#define GEMM2_SMEM (2 * STAGE2_B)        // 61440

__global__ void __launch_bounds__(256, 2)
cls_gemm_mma(const __nv_bfloat16* __restrict__ whi,
             const __nv_bfloat16* __restrict__ wlo,
             const __nv_bfloat16* __restrict__ ahi,
             const __nv_bfloat16* __restrict__ alo,
             float* __restrict__ part) {
    extern __shared__ char sm[];
    int t = threadIdx.x;
    int lane = t & 31, wid = t >> 5;
    int gid = lane >> 2, tig = lane & 3;
    int wm = wid & 3, wn = wid >> 2;
    int c0 = blockIdx.x * 128, b0 = blockIdx.y * 64, ks = blockIdx.z;
    int kbase = ks * (NK / KSPLIT);

    int r = t >> 2, q = t & 3;           // loader role: row 0..63, quarter 0..3
    float acc[2][4][4];
    #pragma unroll
    for (int i = 0; i < 2; i++)
        #pragma unroll
        for (int j = 0; j < 4; j++)
            #pragma unroll
            for (int e = 0; e < 4; e++) acc[i][j][e] = 0.f;

    int4 rg[6];
    #define LOAD_CHUNK(K0) do {                                               \
        long long wo0 = ((long long)(c0 + r) * NK + (K0)) * 2 + q * 16;       \
        long long wo1 = ((long long)(c0 + r + 64) * NK + (K0)) * 2 + q * 16;  \
        long long ao  = ((long long)(b0 + r) * NK + (K0)) * 2 + q * 16;       \
        rg[0] = *(const int4*)((const char*)whi + wo0);                       \
        rg[1] = *(const int4*)((const char*)whi + wo1);                       \
        rg[2] = *(const int4*)((const char*)wlo + wo0);                       \
        rg[3] = *(const int4*)((const char*)wlo + wo1);                       \
        rg[4] = *(const int4*)((const char*)ahi + ao);                        \
        rg[5] = *(const int4*)((const char*)alo + ao);                        \
    } while (0)
    #define STORE_CHUNK(BUF) do {                                             \
        char* s_ = sm + (BUF) * STAGE2_B;                                     \
        *(int4*)(s_ + WHI_OFF + r * SROW + q * 16) = rg[0];                   \
        *(int4*)(s_ + WHI_OFF + (r + 64) * SROW + q * 16) = rg[1];            \
        *(int4*)(s_ + WLO_OFF + r * SROW + q * 16) = rg[2];                   \
        *(int4*)(s_ + WLO_OFF + (r + 64) * SROW + q * 16) = rg[3];            \
        *(int4*)(s_ + AHI_OFF + r * SROW + q * 16) = rg[4];                   \
        *(int4*)(s_ + ALO_OFF + r * SROW + q * 16) = rg[5];                   \
    } while (0)

    LOAD_CHUNK(kbase);
    STORE_CHUNK(0);
    __syncthreads();

    for (int j = 0; j < KCH; j++) {
        if (j + 1 < KCH) LOAD_CHUNK(kbase + (j + 1) * 32);
        const char* s_ = sm + (j & 1) * STAGE2_B;
        #pragma unroll
        for (int s = 0; s < 2; s++) {
            int kb = s * 32 + tig * 4;   // byte offset of (k16 step s, tig*2 elems)
            uint32_t wa[2][4], wl[2][4];
            #pragma unroll
            for (int i = 0; i < 2; i++) {
                int cr = wm * 32 + i * 16 + gid;
                const char* wr = s_ + WHI_OFF + cr * SROW;
                wa[i][0] = *(const uint32_t*)(wr + kb);
                wa[i][1] = *(const uint32_t*)(wr + 8 * SROW + kb);
                wa[i][2] = *(const uint32_t*)(wr + kb + 16);
                wa[i][3] = *(const uint32_t*)(wr + 8 * SROW + kb + 16);
                const char* lr = s_ + WLO_OFF + cr * SROW;
                wl[i][0] = *(const uint32_t*)(lr + kb);
                wl[i][1] = *(const uint32_t*)(lr + 8 * SROW + kb);
                wl[i][2] = *(const uint32_t*)(lr + kb + 16);
                wl[i][3] = *(const uint32_t*)(lr + 8 * SROW + kb + 16);
            }
            #pragma unroll
            for (int jj = 0; jj < 4; jj++) {
                int br = wn * 32 + jj * 8 + gid;
                const char* ar = s_ + AHI_OFF + br * SROW;
                const char* orow = s_ + ALO_OFF + br * SROW;
                uint32_t bh[2], bl[2];
                bh[0] = *(const uint32_t*)(ar + kb);
                bh[1] = *(const uint32_t*)(ar + kb + 16);
                bl[0] = *(const uint32_t*)(orow + kb);
                bl[1] = *(const uint32_t*)(orow + kb + 16);
                mma16816(acc[0][jj], wa[0], bh);
                mma16816(acc[1][jj], wa[1], bh);
                mma16816(acc[0][jj], wa[0], bl);
                mma16816(acc[1][jj], wa[1], bl);
                mma16816(acc[0][jj], wl[0], bh);
                mma16816(acc[1][jj], wl[1], bh);
            }
        }
        if (j + 1 < KCH) STORE_CHUNK((j + 1) & 1);
        __syncthreads();
    }

    // epilogue: c-frag layout c0,c1: (row gid, col 2tig,+1); c2,c3: row gid+8
    #pragma unroll
    for (int i = 0; i < 2; i++) {
        int c = c0 + wm * 32 + i * 16 + gid;
        #pragma unroll
        for (int jj = 0; jj < 4; jj++) {
            int b = b0 + wn * 32 + jj * 8 + 2 * tig;
            float2 lo = make_float2(acc[i][jj][0], acc[i][jj][1]);
            float2 hi = make_float2(acc[i][jj][2], acc[i][jj][3]);
            *(float2*)(part + ((long long)ks * NCLSP + c) * BATCH + b) = lo;
            *(float2*)(part + ((long long)ks * NCLSP + c + 8) * BATCH + b) = hi;
        }
    }
    #undef LOAD_CHUNK
    #undef STORE_CHUNK
}

// ---------------- split-K reduce + bias ----------------
__global__ void reduce_kernel(const float* __restrict__ part,
                              const float* __restrict__ b_cls,
                              float* __restrict__ out) {
    int id = blockIdx.x * blockDim.x + threadIdx.x;
    int b = id & (BATCH - 1);
    int c = id >> 8;
    if (c >= NCLS) return;
    float acc = b_cls[c];
    #pragma unroll
    for (int ks = 0; ks < KSPLIT; ks++)
        acc += part[((long long)ks * NCLSP + c) * BATCH + b];
    out[(long long)b * NCLS + c] = acc;
}

// ---------------- launch ----------------
extern "C" void kernel_launch(void* const* d_in, const int* in_sizes, int n_in,
                              void* d_out, int out_size) {
    const float* x        = (const float*)d_in[0];
    const float* w_ret    = (const float*)d_in[1];
    const float* b_ret    = (const float*)d_in[2];
    const float* w_lgn    = (const float*)d_in[3];
    const float* b_lgn    = (const float*)d_in[4];
    const float* w_v1     = (const float*)d_in[5];
    const float* b_v1     = (const float*)d_in[6];
    const float* w_it     = (const float*)d_in[7];
    const float* b_it     = (const float*)d_in[8];
    const float* W_cls    = (const float*)d_in[9];
    const float* b_cls    = (const float*)d_in[10];
    const int*   pixel_map= (const int*)d_in[11];
    const int*   m1       = (const int*)d_in[12];
    const int*   m2       = (const int*)d_in[13];
    float* out = (float*)d_out;

    __half2* r2t2 = nullptr; __half2* r3t2 = nullptr; float* r4t = nullptr;
    float* sums = nullptr; float* partp = nullptr;
    int *idx1 = nullptr, *cnt1 = nullptr, *idx2 = nullptr, *cnt2 = nullptr;
    __nv_bfloat16 *whi = nullptr, *wlo = nullptr, *ahi = nullptr, *alo = nullptr;
    cudaGetSymbolAddress((void**)&r2t2, g_r2t2);
    cudaGetSymbolAddress((void**)&r3t2, g_r3t2);
    cudaGetSymbolAddress((void**)&r4t,  g_r4t);
    cudaGetSymbolAddress((void**)&sums, g_sums);
    cudaGetSymbolAddress((void**)&partp,g_part);
    cudaGetSymbolAddress((void**)&idx1, g_idx1);
    cudaGetSymbolAddress((void**)&cnt1, g_cnt1);
    cudaGetSymbolAddress((void**)&idx2, g_idx2);
    cudaGetSymbolAddress((void**)&cnt2, g_cnt2);
    cudaGetSymbolAddress((void**)&whi,  g_whi);
    cudaGetSymbolAddress((void**)&wlo,  g_wlo);
    cudaGetSymbolAddress((void**)&ahi,  g_ahi);
    cudaGetSymbolAddress((void**)&alo,  g_alo);

    // unconditional + idempotent (no static guard — harness rule)
    cudaFuncSetAttribute(cls_gemm_mma,
                         cudaFuncAttributeMaxDynamicSharedMemorySize, GEMM2_SMEM);

    // phase 1: retina+LGN, CSR builds, weight sums, W bf16 split
    {
        int nblk = RET_BLKS + CSR1_BLKS + CSR2_BLKS + SUMS_BLKS + WPREP_BLKS;
        phase1_kernel<<<nblk, 256>>>(x, pixel_map, w_ret, b_ret, w_lgn, b_lgn,
                                     w_v1, w_it, W_cls, m1, m2, (__half*)r2t2,
                                     sums, idx1, cnt1, idx2, cnt2, whi, wlo);
    }
    // V1
    spmm_act_h2h<<<NV1 / 2, 256>>>(idx1, cnt1, MAX1, r2t2,
                                   sums + NRET, b_v1, r3t2);
    // IT
    spmm_act_h2f<<<NIT / 2, 256>>>(idx2, cnt2, MAX2, r3t2,
                                   sums + NRET + NV1, b_it, r4t);
    // acts transpose + split
    {
        dim3 grid(NK / 32, BATCH / 32);
        prep_acts_kernel<<<grid, 256>>>(r4t, ahi, alo);
    }
    // classifier on tensor cores (mma.sync)
    {
        dim3 grid(NCLSP / 128, BATCH / 64, KSPLIT);
        cls_gemm_mma<<<grid, 256, GEMM2_SMEM>>>(whi, wlo, ahi, alo, partp);
    }
    reduce_kernel<<<(NCLSP * BATCH + 255) / 256, 256>>>(partp, b_cls, out);
    (void)in_sizes; (void)n_in; (void)out_size;
}